// round 16
// baseline (speedup 1.0000x reference)
#include <cuda_runtime.h>
#include <cuda_fp16.h>
#include <cstdint>

#define NN   50000
#define EE   800000
#define MT   391          // ceil(NN/128)
#define SB   98           // scan blocks (512 each)
#define HROWS 25088       // 196 m-tiles * 128
#define HT0   196         // h0 m-tiles
#define HT1   195         // h1 m-tiles

// ---------------- scratch ----------------
__device__ int      g_cnt[NN];
__device__ int      g_off[NN + 1];
__device__ int      g_cur[NN];
__device__ int      g_csr[EE];
__device__ int      g_bsum[SB];
__device__ float    g_T[NN * 128];            // fp32 self half
__device__ uint32_t g_Tn[NN * 64];            // half2 neighbor payload
__device__ uint32_t g_Ah[MT * 128 * 64];      // activation images bf16x2-hi [row][k2]
__device__ uint32_t g_Al[MT * 128 * 64];
__device__ uint32_t g_Wh[2 * 16384 + 8192];   // weights bf16x2 [k2][n]
__device__ uint32_t g_Wl[2 * 16384 + 8192];

// ---------------- bf16 helpers ----------------
__device__ __forceinline__ uint32_t pack_bf2(float lo, float hi) {
    uint32_t r;
    asm("cvt.rn.bf16x2.f32 %0, %1, %2;" : "=r"(r) : "f"(hi), "f"(lo));
    return r;
}
__device__ __forceinline__ void split_pair(float a, float b, uint32_t& h, uint32_t& l) {
    h = pack_bf2(a, b);
    float ha = __uint_as_float(h << 16);
    float hb = __uint_as_float(h & 0xffff0000u);
    l = pack_bf2(a - ha, b - hb);
}
__device__ __forceinline__ void mma16(float* c, const uint32_t* a, const uint32_t* b) {
    asm volatile(
        "mma.sync.aligned.m16n8k16.row.col.f32.bf16.bf16.f32 "
        "{%0,%1,%2,%3}, {%4,%5,%6,%7}, {%8,%9}, {%0,%1,%2,%3};\n"
        : "+f"(c[0]), "+f"(c[1]), "+f"(c[2]), "+f"(c[3])
        : "r"(a[0]), "r"(a[1]), "r"(a[2]), "r"(a[3]), "r"(b[0]), "r"(b[1]));
}

// ---------------- prep: weight/x conversion ----------------
__global__ void k_prep(const float* __restrict__ x,
                       const float* __restrict__ Ws0, const float* __restrict__ Wn0,
                       const float* __restrict__ Ws1, const float* __restrict__ Wn1,
                       const float* __restrict__ Ws2, const float* __restrict__ Wn2) {
    int id = blockIdx.x * blockDim.x + threadIdx.x;
    if (id < 40960) {
        int l, local, wbase, nw;
        if (id < 16384)      { l = 0; local = id;         wbase = 0;     nw = 256; }
        else if (id < 32768) { l = 1; local = id - 16384; wbase = 16384; nw = 256; }
        else                 { l = 2; local = id - 32768; wbase = 32768; nw = 128; }
        int k2 = local / nw, n = local % nw, k = k2 * 2, d = nw >> 1;
        float v0, v1;
        if (l == 0) {
            v0 = (n < d) ? Ws0[k * d + n] : Wn0[k * d + n - d];
            v1 = (n < d) ? Ws0[(k + 1) * d + n] : Wn0[(k + 1) * d + n - d];
        } else if (l == 1) {
            v0 = (n < d) ? Ws1[k * d + n] : Wn1[k * d + n - d];
            v1 = (n < d) ? Ws1[(k + 1) * d + n] : Wn1[(k + 1) * d + n - d];
        } else {
            v0 = (n < d) ? Ws2[k * d + n] : Wn2[k * d + n - d];
            v1 = (n < d) ? Ws2[(k + 1) * d + n] : Wn2[(k + 1) * d + n - d];
        }
        uint32_t h, lo;
        split_pair(v0, v1, h, lo);
        g_Wh[wbase + k2 * nw + n] = h;
        g_Wl[wbase + k2 * nw + n] = lo;
    }
    if (id < NN * 64) {
        int n = id >> 6, k2 = id & 63;
        float2 v = *reinterpret_cast<const float2*>(x + n * 128 + k2 * 2);
        uint32_t h, lo;
        split_pair(v.x, v.y, h, lo);
        g_Ah[n * 64 + k2] = h;
        g_Al[n * 64 + k2] = lo;
    }
}

// ---------------- CSR build (side stream) ----------------
__global__ void k_zero() {
    int i = blockIdx.x * blockDim.x + threadIdx.x;
    if (i < NN) g_cnt[i] = 0;
}
__global__ void k_hist(const int* __restrict__ dst) {
    int e = blockIdx.x * blockDim.x + threadIdx.x;
    if (e < EE) atomicAdd(&g_cnt[dst[e]], 1);
}
__global__ __launch_bounds__(512) void k_scanA() {
    __shared__ int ss[512];
    int t = threadIdx.x, i = blockIdx.x * 512 + t;
    ss[t] = (i < NN) ? g_cnt[i] : 0;
    __syncthreads();
    for (int d = 256; d > 0; d >>= 1) {
        if (t < d) ss[t] += ss[t + d];
        __syncthreads();
    }
    if (t == 0) g_bsum[blockIdx.x] = ss[0];
}
__global__ __launch_bounds__(512) void k_scanC() {
    __shared__ int bs[128];
    __shared__ int ss[512];
    int t = threadIdx.x, i = blockIdx.x * 512 + t;
    if (t < 128) bs[t] = (t < SB) ? g_bsum[t] : 0;
    int v0 = (i < NN) ? g_cnt[i] : 0;
    ss[t] = v0;
    __syncthreads();
    for (int d = 1; d < 128; d <<= 1) {
        int v = (t < 128 && t >= d) ? bs[t - d] : 0;
        __syncthreads();
        if (t < 128) bs[t] += v;
        __syncthreads();
    }
    for (int d = 1; d < 512; d <<= 1) {
        int v = (t >= d) ? ss[t - d] : 0;
        __syncthreads();
        ss[t] += v;
        __syncthreads();
    }
    if (i < NN) {
        int base = (blockIdx.x > 0) ? bs[blockIdx.x - 1] : 0;
        int off = base + ss[t] - v0;
        g_off[i] = off;
        g_cur[i] = off;
    }
    if (i == NN - 1) g_off[NN] = EE;
}
__global__ void k_scatter(const int* __restrict__ src, const int* __restrict__ dst) {
    int e = blockIdx.x * blockDim.x + threadIdx.x;
    if (e < EE) {
        int p = atomicAdd(&g_cur[dst[e]], 1);
        g_csr[p] = src[e];
    }
}

// ---------------- GEMM: 128 x NC tile, 512 threads, double-buffered smem -----
// mt0: m-tile offset (for half-grid pipelining).
template <int NC>
__global__ __launch_bounds__(512) void k_gemm(int wb, int dsplit, int tn_str, int mt0) {
    constexpr int NT = NC / 32;
    constexpr int BP = NC + 8;
    constexpr int NB = NC / 128;

    extern __shared__ uint32_t sm[];
    uint32_t (*As_h)[20] = reinterpret_cast<uint32_t(*)[20]>(sm);
    uint32_t (*As_l)[20] = reinterpret_cast<uint32_t(*)[20]>(sm + 5120);
    uint32_t (*Bs_h)[BP] = reinterpret_cast<uint32_t(*)[BP]>(sm + 10240);
    uint32_t (*Bs_l)[BP] = reinterpret_cast<uint32_t(*)[BP]>(sm + 10240 + 32 * BP);

    int tid  = threadIdx.x;
    int bm   = (mt0 + blockIdx.x) * 128;
    int warp = tid >> 5, lane = tid & 31;
    int wm = (warp & 3) * 32;
    int wn = (warp >> 2) * (NC / 4);
    int gi = lane >> 2;
    int ti = lane & 3;

    const uint4* GA_h = reinterpret_cast<const uint4*>(g_Ah);
    const uint4* GA_l = reinterpret_cast<const uint4*>(g_Al);
    const uint4* GW_h = reinterpret_cast<const uint4*>(g_Wh);
    const uint4* GW_l = reinterpret_cast<const uint4*>(g_Wl);
    int wb4 = wb >> 2;

    int a_row = tid >> 2, a_q = tid & 3;

    float c[2][NT][4];
#pragma unroll
    for (int mt = 0; mt < 2; ++mt)
#pragma unroll
        for (int nt = 0; nt < NT; ++nt)
#pragma unroll
            for (int i = 0; i < 4; ++i) c[mt][nt][i] = 0.f;

    uint4 pAh, pAl, pBh[NB], pBl[NB];

#define PREF(kc)                                                                  \
    do {                                                                          \
        pAh = GA_h[(bm + a_row) * 16 + (kc) * 4 + a_q];                           \
        pAl = GA_l[(bm + a_row) * 16 + (kc) * 4 + a_q];                           \
        _Pragma("unroll")                                                         \
        for (int j = 0; j < NB; ++j) {                                            \
            int idx = tid + j * 512;                                              \
            int kr = idx / (NC / 4), c4 = idx % (NC / 4);                         \
            pBh[j] = GW_h[wb4 + (((kc) * 16 + kr) * NC >> 2) + c4];               \
            pBl[j] = GW_l[wb4 + (((kc) * 16 + kr) * NC >> 2) + c4];               \
        }                                                                         \
    } while (0)

#define STAGE(buf)                                                                \
    do {                                                                          \
        *reinterpret_cast<uint4*>(&As_h[(buf) * 128 + a_row][a_q * 4]) = pAh;     \
        *reinterpret_cast<uint4*>(&As_l[(buf) * 128 + a_row][a_q * 4]) = pAl;     \
        _Pragma("unroll")                                                         \
        for (int j = 0; j < NB; ++j) {                                            \
            int idx = tid + j * 512;                                              \
            int kr = idx / (NC / 4), c4 = idx % (NC / 4);                         \
            *reinterpret_cast<uint4*>(&Bs_h[(buf) * 16 + kr][c4 * 4]) = pBh[j];   \
            *reinterpret_cast<uint4*>(&Bs_l[(buf) * 16 + kr][c4 * 4]) = pBl[j];   \
        }                                                                         \
    } while (0)

    PREF(0);
    STAGE(0);
    __syncthreads();
    PREF(1);

#pragma unroll
    for (int kc = 0; kc < 4; ++kc) {
        int bA = (kc & 1) * 128;
        int bB = (kc & 1) * 16;

        if (kc < 3) STAGE((kc + 1) & 1);
        if (kc < 2) PREF(kc + 2);

#pragma unroll
        for (int st = 0; st < 2; ++st) {
            int kb2 = st * 8;
            uint32_t ah[2][4], al[2][4];
#pragma unroll
            for (int mt = 0; mt < 2; ++mt) {
                int rb = bA + wm + mt * 16 + gi;
                ah[mt][0] = As_h[rb][kb2 + ti];
                ah[mt][1] = As_h[rb + 8][kb2 + ti];
                ah[mt][2] = As_h[rb][kb2 + ti + 4];
                ah[mt][3] = As_h[rb + 8][kb2 + ti + 4];
                al[mt][0] = As_l[rb][kb2 + ti];
                al[mt][1] = As_l[rb + 8][kb2 + ti];
                al[mt][2] = As_l[rb][kb2 + ti + 4];
                al[mt][3] = As_l[rb + 8][kb2 + ti + 4];
            }
#pragma unroll
            for (int nt = 0; nt < NT; ++nt) {
                int cb = wn + nt * 8 + gi;
                uint32_t bh[2], bl[2];
                bh[0] = Bs_h[bB + kb2 + ti][cb];
                bh[1] = Bs_h[bB + kb2 + ti + 4][cb];
                bl[0] = Bs_l[bB + kb2 + ti][cb];
                bl[1] = Bs_l[bB + kb2 + ti + 4][cb];
#pragma unroll
                for (int mt = 0; mt < 2; ++mt) {
                    mma16(c[mt][nt], ah[mt], bh);
                    mma16(c[mt][nt], al[mt], bh);
                    mma16(c[mt][nt], ah[mt], bl);
                }
            }
        }
        __syncthreads();
    }
#undef PREF
#undef STAGE

    // epilogue: self cols -> fp32 g_T; neighbor cols -> half2 g_Tn
#pragma unroll
    for (int mt = 0; mt < 2; ++mt) {
        int r0 = bm + wm + mt * 16 + gi;
        int r1 = r0 + 8;
#pragma unroll
        for (int nt = 0; nt < NT; ++nt) {
            int colg = wn + nt * 8 + ti * 2;
            if (colg < dsplit) {
                if (r0 < NN)
                    *reinterpret_cast<float2*>(g_T + r0 * dsplit + colg) =
                        make_float2(c[mt][nt][0], c[mt][nt][1]);
                if (r1 < NN)
                    *reinterpret_cast<float2*>(g_T + r1 * dsplit + colg) =
                        make_float2(c[mt][nt][2], c[mt][nt][3]);
            } else {
                int pc = (colg - dsplit) >> 1;
                if (r0 < NN) {
                    __half2 h2 = __floats2half2_rn(c[mt][nt][0], c[mt][nt][1]);
                    g_Tn[r0 * tn_str + pc] = *reinterpret_cast<uint32_t*>(&h2);
                }
                if (r1 < NN) {
                    __half2 h2 = __floats2half2_rn(c[mt][nt][2], c[mt][nt][3]);
                    g_Tn[r1 * tn_str + pc] = *reinterpret_cast<uint32_t*>(&h2);
                }
            }
        }
    }
}

// ---------------- finish (node range [n0, n1)) ----------------
__global__ __launch_bounds__(256) void k_finish(const float* __restrict__ bias,
                                                float* __restrict__ outext, int mode,
                                                int n0, int n1) {
    int warp = threadIdx.x >> 5, lane = threadIdx.x & 31;
    int n = n0 + blockIdx.x * 8 + warp;
    if (n >= n1) return;
    int s0 = g_off[n], s1 = g_off[n + 1];
    float inv = 1.0f / (float)((s1 - s0) > 0 ? (s1 - s0) : 1);

    if (mode == 0) {
        float4 acc = make_float4(0.f, 0.f, 0.f, 0.f);
        float4 ac2 = make_float4(0.f, 0.f, 0.f, 0.f);
        int i = s0;
        for (; i + 2 <= s1; i += 2) {
            int sa = g_csr[i], sb = g_csr[i + 1];
            uint2 va = *reinterpret_cast<const uint2*>(g_Tn + sa * 64 + lane * 2);
            uint2 vb = *reinterpret_cast<const uint2*>(g_Tn + sb * 64 + lane * 2);
            float2 a0 = __half22float2(*reinterpret_cast<__half2*>(&va.x));
            float2 a1 = __half22float2(*reinterpret_cast<__half2*>(&va.y));
            float2 b0 = __half22float2(*reinterpret_cast<__half2*>(&vb.x));
            float2 b1 = __half22float2(*reinterpret_cast<__half2*>(&vb.y));
            acc.x += a0.x; acc.y += a0.y; acc.z += a1.x; acc.w += a1.y;
            ac2.x += b0.x; ac2.y += b0.y; ac2.z += b1.x; ac2.w += b1.y;
        }
        if (i < s1) {
            uint2 va = *reinterpret_cast<const uint2*>(g_Tn + g_csr[i] * 64 + lane * 2);
            float2 a0 = __half22float2(*reinterpret_cast<__half2*>(&va.x));
            float2 a1 = __half22float2(*reinterpret_cast<__half2*>(&va.y));
            acc.x += a0.x; acc.y += a0.y; acc.z += a1.x; acc.w += a1.y;
        }
        acc.x += ac2.x; acc.y += ac2.y; acc.z += ac2.z; acc.w += ac2.w;
        float4 p = *reinterpret_cast<const float4*>(g_T + n * 128 + lane * 4);
        float4 b = *reinterpret_cast<const float4*>(bias + lane * 4);
        float4 r;
        r.x = fmaxf(p.x + acc.x * inv + b.x, 0.f);
        r.y = fmaxf(p.y + acc.y * inv + b.y, 0.f);
        r.z = fmaxf(p.z + acc.z * inv + b.z, 0.f);
        r.w = fmaxf(p.w + acc.w * inv + b.w, 0.f);
        uint32_t h0, l0, h1, l1;
        split_pair(r.x, r.y, h0, l0);
        split_pair(r.z, r.w, h1, l1);
        int i0 = n * 64 + lane * 2;
        g_Ah[i0] = h0;     g_Al[i0] = l0;
        g_Ah[i0 + 1] = h1; g_Al[i0 + 1] = l1;
    } else {
        float2 acc = make_float2(0.f, 0.f);
        float2 ac2 = make_float2(0.f, 0.f);
        int i = s0;
        for (; i + 2 <= s1; i += 2) {
            uint32_t va = g_Tn[g_csr[i] * 32 + lane];
            uint32_t vb = g_Tn[g_csr[i + 1] * 32 + lane];
            float2 a = __half22float2(*reinterpret_cast<__half2*>(&va));
            float2 b = __half22float2(*reinterpret_cast<__half2*>(&vb));
            acc.x += a.x; acc.y += a.y;
            ac2.x += b.x; ac2.y += b.y;
        }
        if (i < s1) {
            uint32_t va = g_Tn[g_csr[i] * 32 + lane];
            float2 a = __half22float2(*reinterpret_cast<__half2*>(&va));
            acc.x += a.x; acc.y += a.y;
        }
        acc.x += ac2.x; acc.y += ac2.y;
        float2 p = *reinterpret_cast<const float2*>(g_T + n * 64 + lane * 2);
        float2 b = *reinterpret_cast<const float2*>(bias + lane * 2);
        float2 r;
        r.x = p.x + acc.x * inv + b.x;
        r.y = p.y + acc.y * inv + b.y;
        *reinterpret_cast<float2*>(outext + n * 64 + lane * 2) = r;
    }
}

// ---------------- launch ----------------
extern "C" void kernel_launch(void* const* d_in, const int* in_sizes, int n_in,
                              void* d_out, int out_size) {
    const float* x   = (const float*)d_in[0];
    const int*   src = (const int*)d_in[1];
    const int*   dst = (const int*)d_in[2];
    const float* Ws0 = (const float*)d_in[3];
    const float* Wn0 = (const float*)d_in[4];
    const float* b0  = (const float*)d_in[5];
    const float* Ws1 = (const float*)d_in[6];
    const float* Wn1 = (const float*)d_in[7];
    const float* b1  = (const float*)d_in[8];
    const float* Ws2 = (const float*)d_in[9];
    const float* Wn2 = (const float*)d_in[10];
    const float* b2  = (const float*)d_in[11];
    float* out = (float*)d_out;

    const int SM256 = (10240 + 2 * 32 * 264) * 4;   // 108544
    const int SM128 = (10240 + 2 * 32 * 136) * 4;   // 75776
    cudaFuncSetAttribute(k_gemm<256>, cudaFuncAttributeMaxDynamicSharedMemorySize, SM256);
    cudaFuncSetAttribute(k_gemm<128>, cudaFuncAttributeMaxDynamicSharedMemorySize, SM128);

    cudaStream_t s2;
    cudaStreamCreateWithFlags(&s2, cudaStreamNonBlocking);
    cudaEvent_t evStart, evCSR, evA, evC, evD, evF;
    cudaEventCreateWithFlags(&evStart, cudaEventDisableTiming);
    cudaEventCreateWithFlags(&evCSR, cudaEventDisableTiming);
    cudaEventCreateWithFlags(&evA, cudaEventDisableTiming);
    cudaEventCreateWithFlags(&evC, cudaEventDisableTiming);
    cudaEventCreateWithFlags(&evD, cudaEventDisableTiming);
    cudaEventCreateWithFlags(&evF, cudaEventDisableTiming);

    // fork: CSR build on side stream, concurrent with prep + layer-0 GEMM
    cudaEventRecord(evStart, 0);
    cudaStreamWaitEvent(s2, evStart, 0);
    k_zero<<<(NN + 255) / 256, 256, 0, s2>>>();
    k_hist<<<(EE + 255) / 256, 256, 0, s2>>>(dst);
    k_scanA<<<SB, 512, 0, s2>>>();
    k_scanC<<<SB, 512, 0, s2>>>();
    k_scatter<<<(EE + 255) / 256, 256, 0, s2>>>(src, dst);
    cudaEventRecord(evCSR, s2);

    // main stream: prep + full layer-0 GEMM
    k_prep<<<(NN * 64 + 255) / 256, 256>>>(x, Ws0, Wn0, Ws1, Wn1, Ws2, Wn2);
    k_gemm<256><<<MT, 512, SM256>>>(0, 128, 64, 0);
    cudaStreamWaitEvent(0, evCSR, 0);

    const int FB0 = HROWS / 8;                 // 3136
    const int FB1 = (NN - HROWS + 7) / 8;      // 3114

    // ---- boundary 0->1: finish halves pipelined with gemm1 halves ----
    k_finish<<<FB0, 256>>>(b0, nullptr, 0, 0, HROWS);
    cudaEventRecord(evA, 0);
    k_finish<<<FB1, 256>>>(b0, nullptr, 0, HROWS, NN);
    // side stream: gemm1 half0 overlaps finish half1
    cudaStreamWaitEvent(s2, evA, 0);
    k_gemm<256><<<HT0, 512, SM256, s2>>>(16384, 128, 64, 0);
    cudaEventRecord(evC, s2);
    // main: gemm1 half1 (after finish h1 in-stream)
    k_gemm<256><<<HT1, 512, SM256>>>(16384, 128, 64, HT0);
    cudaStreamWaitEvent(0, evC, 0);

    // ---- boundary 1->2 ----
    k_finish<<<FB0, 256>>>(b1, nullptr, 0, 0, HROWS);
    cudaEventRecord(evD, 0);
    k_finish<<<FB1, 256>>>(b1, nullptr, 0, HROWS, NN);
    cudaStreamWaitEvent(s2, evD, 0);
    k_gemm<128><<<HT0, 512, SM128, s2>>>(32768, 64, 32, 0);
    cudaEventRecord(evF, s2);
    k_gemm<128><<<HT1, 512, SM128>>>(32768, 64, 32, HT0);
    cudaStreamWaitEvent(0, evF, 0);

    // final finish (full range)
    k_finish<<<(NN + 7) / 8, 256>>>(b2, out, 2, 0, NN);
}

// round 17
// speedup vs baseline: 1.0538x; 1.0538x over previous
#include <cuda_runtime.h>
#include <cuda_fp16.h>
#include <cstdint>

#define NN   50000
#define EE   800000
#define MT   391          // ceil(NN/128)
#define SB   98           // scan blocks (512 each)

// ---------------- scratch ----------------
__device__ int      g_cnt[NN];
__device__ int      g_off[NN + 1];
__device__ int      g_cur[NN];
__device__ int      g_csr[EE];
__device__ int      g_bsum[SB];
__device__ float    g_T[NN * 128];            // fp32 self half
__device__ uint32_t g_Tn[NN * 64];            // half2 neighbor payload
__device__ uint32_t g_Ah[MT * 128 * 64];      // activation images (layers 1-2 only)
__device__ uint32_t g_Al[MT * 128 * 64];
__device__ uint32_t g_Wh[2 * 16384 + 8192];   // weights bf16x2 [k2][n]
__device__ uint32_t g_Wl[2 * 16384 + 8192];

// ---------------- bf16 helpers ----------------
__device__ __forceinline__ uint32_t pack_bf2(float lo, float hi) {
    uint32_t r;
    asm("cvt.rn.bf16x2.f32 %0, %1, %2;" : "=r"(r) : "f"(hi), "f"(lo));
    return r;
}
__device__ __forceinline__ void split_pair(float a, float b, uint32_t& h, uint32_t& l) {
    h = pack_bf2(a, b);
    float ha = __uint_as_float(h << 16);
    float hb = __uint_as_float(h & 0xffff0000u);
    l = pack_bf2(a - ha, b - hb);
}
__device__ __forceinline__ void mma16(float* c, const uint32_t* a, const uint32_t* b) {
    asm volatile(
        "mma.sync.aligned.m16n8k16.row.col.f32.bf16.bf16.f32 "
        "{%0,%1,%2,%3}, {%4,%5,%6,%7}, {%8,%9}, {%0,%1,%2,%3};\n"
        : "+f"(c[0]), "+f"(c[1]), "+f"(c[2]), "+f"(c[3])
        : "r"(a[0]), "r"(a[1]), "r"(a[2]), "r"(a[3]), "r"(b[0]), "r"(b[1]));
}

// ---------------- prep: weight conversion only ----------------
__global__ void k_prep(const float* __restrict__ Ws0, const float* __restrict__ Wn0,
                       const float* __restrict__ Ws1, const float* __restrict__ Wn1,
                       const float* __restrict__ Ws2, const float* __restrict__ Wn2) {
    int id = blockIdx.x * blockDim.x + threadIdx.x;
    if (id >= 40960) return;
    int l, local, wbase, nw;
    if (id < 16384)      { l = 0; local = id;         wbase = 0;     nw = 256; }
    else if (id < 32768) { l = 1; local = id - 16384; wbase = 16384; nw = 256; }
    else                 { l = 2; local = id - 32768; wbase = 32768; nw = 128; }
    int k2 = local / nw, n = local % nw, k = k2 * 2, d = nw >> 1;
    float v0, v1;
    if (l == 0) {
        v0 = (n < d) ? Ws0[k * d + n] : Wn0[k * d + n - d];
        v1 = (n < d) ? Ws0[(k + 1) * d + n] : Wn0[(k + 1) * d + n - d];
    } else if (l == 1) {
        v0 = (n < d) ? Ws1[k * d + n] : Wn1[k * d + n - d];
        v1 = (n < d) ? Ws1[(k + 1) * d + n] : Wn1[(k + 1) * d + n - d];
    } else {
        v0 = (n < d) ? Ws2[k * d + n] : Wn2[k * d + n - d];
        v1 = (n < d) ? Ws2[(k + 1) * d + n] : Wn2[(k + 1) * d + n - d];
    }
    uint32_t h, lo;
    split_pair(v0, v1, h, lo);
    g_Wh[wbase + k2 * nw + n] = h;
    g_Wl[wbase + k2 * nw + n] = lo;
}

// ---------------- CSR build (side stream) ----------------
__global__ void k_zero() {
    int i = blockIdx.x * blockDim.x + threadIdx.x;
    if (i < NN) g_cnt[i] = 0;
}
__global__ void k_hist(const int* __restrict__ dst) {
    int e = blockIdx.x * blockDim.x + threadIdx.x;
    if (e < EE) atomicAdd(&g_cnt[dst[e]], 1);
}
__global__ __launch_bounds__(512) void k_scanA() {
    __shared__ int ss[512];
    int t = threadIdx.x, i = blockIdx.x * 512 + t;
    ss[t] = (i < NN) ? g_cnt[i] : 0;
    __syncthreads();
    for (int d = 256; d > 0; d >>= 1) {
        if (t < d) ss[t] += ss[t + d];
        __syncthreads();
    }
    if (t == 0) g_bsum[blockIdx.x] = ss[0];
}
__global__ __launch_bounds__(512) void k_scanC() {
    __shared__ int bs[128];
    __shared__ int ss[512];
    int t = threadIdx.x, i = blockIdx.x * 512 + t;
    if (t < 128) bs[t] = (t < SB) ? g_bsum[t] : 0;
    int v0 = (i < NN) ? g_cnt[i] : 0;
    ss[t] = v0;
    __syncthreads();
    for (int d = 1; d < 128; d <<= 1) {
        int v = (t < 128 && t >= d) ? bs[t - d] : 0;
        __syncthreads();
        if (t < 128) bs[t] += v;
        __syncthreads();
    }
    for (int d = 1; d < 512; d <<= 1) {
        int v = (t >= d) ? ss[t - d] : 0;
        __syncthreads();
        ss[t] += v;
        __syncthreads();
    }
    if (i < NN) {
        int base = (blockIdx.x > 0) ? bs[blockIdx.x - 1] : 0;
        int off = base + ss[t] - v0;
        g_off[i] = off;
        g_cur[i] = off;
    }
    if (i == NN - 1) g_off[NN] = EE;
}
__global__ void k_scatter(const int* __restrict__ src, const int* __restrict__ dst) {
    int e = blockIdx.x * blockDim.x + threadIdx.x;
    if (e < EE) {
        int p = atomicAdd(&g_cur[dst[e]], 1);
        g_csr[p] = src[e];
    }
}

// ---------------- GEMM: 128 x NC tile, 512 threads, double-buffered smem -----
// XMODE 0: A from bf16 hi/lo images. XMODE 1: A from fp32 x, split in PREF.
template <int NC, int XMODE>
__global__ __launch_bounds__(512) void k_gemm(int wb, int dsplit, int tn_str,
                                              const float* __restrict__ xp) {
    constexpr int NT = NC / 32;
    constexpr int BP = NC + 8;
    constexpr int NB = NC / 128;

    extern __shared__ uint32_t sm[];
    uint32_t (*As_h)[20] = reinterpret_cast<uint32_t(*)[20]>(sm);
    uint32_t (*As_l)[20] = reinterpret_cast<uint32_t(*)[20]>(sm + 5120);
    uint32_t (*Bs_h)[BP] = reinterpret_cast<uint32_t(*)[BP]>(sm + 10240);
    uint32_t (*Bs_l)[BP] = reinterpret_cast<uint32_t(*)[BP]>(sm + 10240 + 32 * BP);

    int tid  = threadIdx.x;
    int bm   = blockIdx.x * 128;
    int warp = tid >> 5, lane = tid & 31;
    int wm = (warp & 3) * 32;
    int wn = (warp >> 2) * (NC / 4);
    int gi = lane >> 2;
    int ti = lane & 3;

    const uint4* GA_h = reinterpret_cast<const uint4*>(g_Ah);
    const uint4* GA_l = reinterpret_cast<const uint4*>(g_Al);
    const uint4* GW_h = reinterpret_cast<const uint4*>(g_Wh);
    const uint4* GW_l = reinterpret_cast<const uint4*>(g_Wl);
    int wb4 = wb >> 2;

    int a_row = tid >> 2, a_q = tid & 3;
    int a_grow = bm + a_row;
    bool a_ok = a_grow < NN;

    float c[2][NT][4];
#pragma unroll
    for (int mt = 0; mt < 2; ++mt)
#pragma unroll
        for (int nt = 0; nt < NT; ++nt)
#pragma unroll
            for (int i = 0; i < 4; ++i) c[mt][nt][i] = 0.f;

    uint4 pAh, pAl, pBh[NB], pBl[NB];

#define PREF(kc)                                                                  \
    do {                                                                          \
        if (XMODE == 0) {                                                         \
            pAh = GA_h[a_grow * 16 + (kc) * 4 + a_q];                             \
            pAl = GA_l[a_grow * 16 + (kc) * 4 + a_q];                             \
        } else {                                                                  \
            float4 v0 = make_float4(0.f, 0.f, 0.f, 0.f), v1 = v0;                 \
            if (a_ok) {                                                           \
                const float4* X4 = reinterpret_cast<const float4*>(               \
                    xp + a_grow * 128 + (kc) * 32 + a_q * 8);                     \
                v0 = X4[0];                                                       \
                v1 = X4[1];                                                       \
            }                                                                     \
            split_pair(v0.x, v0.y, pAh.x, pAl.x);                                 \
            split_pair(v0.z, v0.w, pAh.y, pAl.y);                                 \
            split_pair(v1.x, v1.y, pAh.z, pAl.z);                                 \
            split_pair(v1.z, v1.w, pAh.w, pAl.w);                                 \
        }                                                                         \
        _Pragma("unroll")                                                         \
        for (int j = 0; j < NB; ++j) {                                            \
            int idx = tid + j * 512;                                              \
            int kr = idx / (NC / 4), c4 = idx % (NC / 4);                         \
            pBh[j] = GW_h[wb4 + (((kc) * 16 + kr) * NC >> 2) + c4];               \
            pBl[j] = GW_l[wb4 + (((kc) * 16 + kr) * NC >> 2) + c4];               \
        }                                                                         \
    } while (0)

#define STAGE(buf)                                                                \
    do {                                                                          \
        *reinterpret_cast<uint4*>(&As_h[(buf) * 128 + a_row][a_q * 4]) = pAh;     \
        *reinterpret_cast<uint4*>(&As_l[(buf) * 128 + a_row][a_q * 4]) = pAl;     \
        _Pragma("unroll")                                                         \
        for (int j = 0; j < NB; ++j) {                                            \
            int idx = tid + j * 512;                                              \
            int kr = idx / (NC / 4), c4 = idx % (NC / 4);                         \
            *reinterpret_cast<uint4*>(&Bs_h[(buf) * 16 + kr][c4 * 4]) = pBh[j];   \
            *reinterpret_cast<uint4*>(&Bs_l[(buf) * 16 + kr][c4 * 4]) = pBl[j];   \
        }                                                                         \
    } while (0)

    PREF(0);
    STAGE(0);
    __syncthreads();
    PREF(1);

#pragma unroll
    for (int kc = 0; kc < 4; ++kc) {
        int bA = (kc & 1) * 128;
        int bB = (kc & 1) * 16;

        if (kc < 3) STAGE((kc + 1) & 1);
        if (kc < 2) PREF(kc + 2);

#pragma unroll
        for (int st = 0; st < 2; ++st) {
            int kb2 = st * 8;
            uint32_t ah[2][4], al[2][4];
#pragma unroll
            for (int mt = 0; mt < 2; ++mt) {
                int rb = bA + wm + mt * 16 + gi;
                ah[mt][0] = As_h[rb][kb2 + ti];
                ah[mt][1] = As_h[rb + 8][kb2 + ti];
                ah[mt][2] = As_h[rb][kb2 + ti + 4];
                ah[mt][3] = As_h[rb + 8][kb2 + ti + 4];
                al[mt][0] = As_l[rb][kb2 + ti];
                al[mt][1] = As_l[rb + 8][kb2 + ti];
                al[mt][2] = As_l[rb][kb2 + ti + 4];
                al[mt][3] = As_l[rb + 8][kb2 + ti + 4];
            }
#pragma unroll
            for (int nt = 0; nt < NT; ++nt) {
                int cb = wn + nt * 8 + gi;
                uint32_t bh[2], bl[2];
                bh[0] = Bs_h[bB + kb2 + ti][cb];
                bh[1] = Bs_h[bB + kb2 + ti + 4][cb];
                bl[0] = Bs_l[bB + kb2 + ti][cb];
                bl[1] = Bs_l[bB + kb2 + ti + 4][cb];
#pragma unroll
                for (int mt = 0; mt < 2; ++mt) {
                    mma16(c[mt][nt], ah[mt], bh);
                    mma16(c[mt][nt], al[mt], bh);
                    mma16(c[mt][nt], ah[mt], bl);
                }
            }
        }
        __syncthreads();
    }
#undef PREF
#undef STAGE

    // epilogue: self cols -> fp32 g_T; neighbor cols -> half2 g_Tn
#pragma unroll
    for (int mt = 0; mt < 2; ++mt) {
        int r0 = bm + wm + mt * 16 + gi;
        int r1 = r0 + 8;
#pragma unroll
        for (int nt = 0; nt < NT; ++nt) {
            int colg = wn + nt * 8 + ti * 2;
            if (colg < dsplit) {
                if (r0 < NN)
                    *reinterpret_cast<float2*>(g_T + r0 * dsplit + colg) =
                        make_float2(c[mt][nt][0], c[mt][nt][1]);
                if (r1 < NN)
                    *reinterpret_cast<float2*>(g_T + r1 * dsplit + colg) =
                        make_float2(c[mt][nt][2], c[mt][nt][3]);
            } else {
                int pc = (colg - dsplit) >> 1;
                if (r0 < NN) {
                    __half2 h2 = __floats2half2_rn(c[mt][nt][0], c[mt][nt][1]);
                    g_Tn[r0 * tn_str + pc] = *reinterpret_cast<uint32_t*>(&h2);
                }
                if (r1 < NN) {
                    __half2 h2 = __floats2half2_rn(c[mt][nt][2], c[mt][nt][3]);
                    g_Tn[r1 * tn_str + pc] = *reinterpret_cast<uint32_t*>(&h2);
                }
            }
        }
    }
}

// ---------------- finish (R11-proven 2-way unroll) ----------------
__global__ __launch_bounds__(256) void k_finish(const float* __restrict__ bias,
                                                float* __restrict__ outext, int mode) {
    int warp = threadIdx.x >> 5, lane = threadIdx.x & 31;
    int n = blockIdx.x * 8 + warp;
    if (n >= NN) return;
    int s0 = g_off[n], s1 = g_off[n + 1];
    float inv = 1.0f / (float)((s1 - s0) > 0 ? (s1 - s0) : 1);

    if (mode == 0) {
        float4 acc = make_float4(0.f, 0.f, 0.f, 0.f);
        float4 ac2 = make_float4(0.f, 0.f, 0.f, 0.f);
        int i = s0;
        for (; i + 2 <= s1; i += 2) {
            int sa = g_csr[i], sb = g_csr[i + 1];
            uint2 va = *reinterpret_cast<const uint2*>(g_Tn + sa * 64 + lane * 2);
            uint2 vb = *reinterpret_cast<const uint2*>(g_Tn + sb * 64 + lane * 2);
            float2 a0 = __half22float2(*reinterpret_cast<__half2*>(&va.x));
            float2 a1 = __half22float2(*reinterpret_cast<__half2*>(&va.y));
            float2 b0 = __half22float2(*reinterpret_cast<__half2*>(&vb.x));
            float2 b1 = __half22float2(*reinterpret_cast<__half2*>(&vb.y));
            acc.x += a0.x; acc.y += a0.y; acc.z += a1.x; acc.w += a1.y;
            ac2.x += b0.x; ac2.y += b0.y; ac2.z += b1.x; ac2.w += b1.y;
        }
        if (i < s1) {
            uint2 va = *reinterpret_cast<const uint2*>(g_Tn + g_csr[i] * 64 + lane * 2);
            float2 a0 = __half22float2(*reinterpret_cast<__half2*>(&va.x));
            float2 a1 = __half22float2(*reinterpret_cast<__half2*>(&va.y));
            acc.x += a0.x; acc.y += a0.y; acc.z += a1.x; acc.w += a1.y;
        }
        acc.x += ac2.x; acc.y += ac2.y; acc.z += ac2.z; acc.w += ac2.w;
        float4 p = *reinterpret_cast<const float4*>(g_T + n * 128 + lane * 4);
        float4 b = *reinterpret_cast<const float4*>(bias + lane * 4);
        float4 r;
        r.x = fmaxf(p.x + acc.x * inv + b.x, 0.f);
        r.y = fmaxf(p.y + acc.y * inv + b.y, 0.f);
        r.z = fmaxf(p.z + acc.z * inv + b.z, 0.f);
        r.w = fmaxf(p.w + acc.w * inv + b.w, 0.f);
        uint32_t h0, l0, h1, l1;
        split_pair(r.x, r.y, h0, l0);
        split_pair(r.z, r.w, h1, l1);
        int i0 = n * 64 + lane * 2;
        g_Ah[i0] = h0;     g_Al[i0] = l0;
        g_Ah[i0 + 1] = h1; g_Al[i0 + 1] = l1;
    } else {
        float2 acc = make_float2(0.f, 0.f);
        float2 ac2 = make_float2(0.f, 0.f);
        int i = s0;
        for (; i + 2 <= s1; i += 2) {
            uint32_t va = g_Tn[g_csr[i] * 32 + lane];
            uint32_t vb = g_Tn[g_csr[i + 1] * 32 + lane];
            float2 a = __half22float2(*reinterpret_cast<__half2*>(&va));
            float2 b = __half22float2(*reinterpret_cast<__half2*>(&vb));
            acc.x += a.x; acc.y += a.y;
            ac2.x += b.x; ac2.y += b.y;
        }
        if (i < s1) {
            uint32_t va = g_Tn[g_csr[i] * 32 + lane];
            float2 a = __half22float2(*reinterpret_cast<__half2*>(&va));
            acc.x += a.x; acc.y += a.y;
        }
        acc.x += ac2.x; acc.y += ac2.y;
        float2 p = *reinterpret_cast<const float2*>(g_T + n * 64 + lane * 2);
        float2 b = *reinterpret_cast<const float2*>(bias + lane * 2);
        float2 r;
        r.x = p.x + acc.x * inv + b.x;
        r.y = p.y + acc.y * inv + b.y;
        *reinterpret_cast<float2*>(outext + n * 64 + lane * 2) = r;
    }
}

// ---------------- launch ----------------
extern "C" void kernel_launch(void* const* d_in, const int* in_sizes, int n_in,
                              void* d_out, int out_size) {
    const float* x   = (const float*)d_in[0];
    const int*   src = (const int*)d_in[1];
    const int*   dst = (const int*)d_in[2];
    const float* Ws0 = (const float*)d_in[3];
    const float* Wn0 = (const float*)d_in[4];
    const float* b0  = (const float*)d_in[5];
    const float* Ws1 = (const float*)d_in[6];
    const float* Wn1 = (const float*)d_in[7];
    const float* b1  = (const float*)d_in[8];
    const float* Ws2 = (const float*)d_in[9];
    const float* Wn2 = (const float*)d_in[10];
    const float* b2  = (const float*)d_in[11];
    float* out = (float*)d_out;

    const int SM256 = (10240 + 2 * 32 * 264) * 4;   // 108544
    const int SM128 = (10240 + 2 * 32 * 136) * 4;   // 75776
    cudaFuncSetAttribute(k_gemm<256, 0>, cudaFuncAttributeMaxDynamicSharedMemorySize, SM256);
    cudaFuncSetAttribute(k_gemm<256, 1>, cudaFuncAttributeMaxDynamicSharedMemorySize, SM256);
    cudaFuncSetAttribute(k_gemm<128, 0>, cudaFuncAttributeMaxDynamicSharedMemorySize, SM128);

    // fork: CSR build on side stream, concurrent with prep + layer-0 GEMM
    cudaStream_t s2;
    cudaStreamCreateWithFlags(&s2, cudaStreamNonBlocking);
    cudaEvent_t evStart, evCSR;
    cudaEventCreateWithFlags(&evStart, cudaEventDisableTiming);
    cudaEventCreateWithFlags(&evCSR, cudaEventDisableTiming);

    cudaEventRecord(evStart, 0);
    cudaStreamWaitEvent(s2, evStart, 0);
    k_zero<<<(NN + 255) / 256, 256, 0, s2>>>();
    k_hist<<<(EE + 255) / 256, 256, 0, s2>>>(dst);
    k_scanA<<<SB, 512, 0, s2>>>();
    k_scanC<<<SB, 512, 0, s2>>>();
    k_scatter<<<(EE + 255) / 256, 256, 0, s2>>>(src, dst);
    cudaEventRecord(evCSR, s2);

    // main stream: weight prep (tiny) + layer-0 GEMM reading x directly
    k_prep<<<160, 256>>>(Ws0, Wn0, Ws1, Wn1, Ws2, Wn2);

    const int FB = (NN + 7) / 8;

    k_gemm<256, 1><<<MT, 512, SM256>>>(0, 128, 64, x);
    cudaStreamWaitEvent(0, evCSR, 0);            // join before first gather
    k_finish<<<FB, 256>>>(b0, nullptr, 0);
    // Layer 1
    k_gemm<256, 0><<<MT, 512, SM256>>>(16384, 128, 64, nullptr);
    k_finish<<<FB, 256>>>(b1, nullptr, 0);
    // Layer 2
    k_gemm<128, 0><<<MT, 512, SM128>>>(32768, 64, 32, nullptr);
    k_finish<<<FB, 256>>>(b2, out, 2);
}